// round 1
// baseline (speedup 1.0000x reference)
#include <cuda_runtime.h>
#include <cstdint>

// Inverse 2D Haar wavelet (synthesis) for fixed shapes:
//   in : (B=32, C4=256, H=64, W=64) f32, where C4 = C*4 (cA,cH,cV,cD interleaved per channel)
//   out: (B=32, C=64, 2H=128, 2W=128) f32
//
// Each thread handles 4 consecutive w positions (one float4 per subband),
// producing 2x8 output pixels (two rows x 8 cols) = 4 float4 stores.

#define IWT_H 64
#define IWT_W 64
#define IWT_C 64

__global__ void __launch_bounds__(256, 8) iwt_kernel(
    const float* __restrict__ x, float* __restrict__ out, int total_groups)
{
    int idx = blockIdx.x * blockDim.x + threadIdx.x;
    if (idx >= total_groups) return;

    // idx -> (bc, h, w4) ; bc = b*C + c flattened (B*C = 2048)
    int w4 = idx & 15;            // W/4 = 16
    int t  = idx >> 4;
    int h  = t & 63;              // H = 64
    int bc = t >> 6;              // 0 .. B*C-1

    // Input: subband s of channel bc lives at plane (bc*4 + s), plane size H*W
    const float4* pA = (const float4*)(x + (size_t)(bc * 4 + 0) * (IWT_H * IWT_W));
    const float4* pH = (const float4*)(x + (size_t)(bc * 4 + 1) * (IWT_H * IWT_W));
    const float4* pV = (const float4*)(x + (size_t)(bc * 4 + 2) * (IWT_H * IWT_W));
    const float4* pD = (const float4*)(x + (size_t)(bc * 4 + 3) * (IWT_H * IWT_W));

    int in_off = h * (IWT_W / 4) + w4;   // float4 index within plane

    float4 a = pA[in_off];
    float4 hh = pH[in_off];
    float4 v = pV[in_off];
    float4 d = pD[in_off];

    // Output plane for channel bc: (2H x 2W) = 128x128
    float* o = out + (size_t)bc * (2 * IWT_H * 2 * IWT_W);
    int r0 = (2 * h) * (2 * IWT_W) + (8 * w4);     // row 2h, col 8*w4
    int r1 = r0 + 2 * IWT_W;                       // row 2h+1

    float4 out00, out01, out10, out11;  // two float4 per output row

    // element i of the input float4 -> output columns 2i, 2i+1
    {
        float ai = a.x, hi = hh.x, vi = v.x, di = d.x;
        out00.x = (ai + hi + vi + di) * 0.5f;
        out00.y = (ai + hi - vi - di) * 0.5f;
        out10.x = (ai - hi + vi - di) * 0.5f;
        out10.y = (ai - hi - vi + di) * 0.5f;
    }
    {
        float ai = a.y, hi = hh.y, vi = v.y, di = d.y;
        out00.z = (ai + hi + vi + di) * 0.5f;
        out00.w = (ai + hi - vi - di) * 0.5f;
        out10.z = (ai - hi + vi - di) * 0.5f;
        out10.w = (ai - hi - vi + di) * 0.5f;
    }
    {
        float ai = a.z, hi = hh.z, vi = v.z, di = d.z;
        out01.x = (ai + hi + vi + di) * 0.5f;
        out01.y = (ai + hi - vi - di) * 0.5f;
        out11.x = (ai - hi + vi - di) * 0.5f;
        out11.y = (ai - hi - vi + di) * 0.5f;
    }
    {
        float ai = a.w, hi = hh.w, vi = v.w, di = d.w;
        out01.z = (ai + hi + vi + di) * 0.5f;
        out01.w = (ai + hi - vi - di) * 0.5f;
        out11.z = (ai - hi + vi - di) * 0.5f;
        out11.w = (ai - hi - vi + di) * 0.5f;
    }

    *(float4*)(o + r0)     = out00;
    *(float4*)(o + r0 + 4) = out01;
    *(float4*)(o + r1)     = out10;
    *(float4*)(o + r1 + 4) = out11;
}

extern "C" void kernel_launch(void* const* d_in, const int* in_sizes, int n_in,
                              void* d_out, int out_size) {
    const float* x = (const float*)d_in[0];
    float* out = (float*)d_out;

    // total elements = B * C*4 * H * W ; groups = elements / 16 (4 subbands x float4)
    int total = in_sizes[0];
    int groups = total / 16;

    int threads = 256;
    int blocks = (groups + threads - 1) / threads;
    iwt_kernel<<<blocks, threads>>>(x, out, groups);
}

// round 2
// speedup vs baseline: 1.0847x; 1.0847x over previous
#include <cuda_runtime.h>
#include <cstdint>

// Inverse 2D Haar wavelet (synthesis), fixed shapes:
//   in : (B=32, C4=256, H=64, W=64) f32   (C4 = C*4: cA,cH,cV,cD per channel)
//   out: (B=32, C=64, 128, 128) f32
//
// Warp-per-input-row mapping for perfectly coalesced stores:
//   lane i loads input cols [2i, 2i+2) of each subband (float2, 256B/warp/subband)
//   lane i stores output cols [4i, 4i+4) of rows 2h and 2h+1 (float4 each,
//   512B fully contiguous per STG.128 instruction).

#define IWT_H 64
#define IWT_W 64
#define PLANE_IN  (IWT_H * IWT_W)          // 4096
#define PLANE_OUT (4 * IWT_H * IWT_W)      // 16384

__global__ void __launch_bounds__(256, 8) iwt_kernel(
    const float* __restrict__ x, float* __restrict__ out)
{
    int t = blockIdx.x * blockDim.x + threadIdx.x;
    int lane = t & 31;
    int w = t >> 5;          // warp index = (bc, h)
    int h = w & 63;
    int bc = w >> 6;         // 0 .. B*C-1 (2048)

    // Input: subband s of channel bc at plane (bc*4 + s)
    const float* base = x + (size_t)bc * 4 * PLANE_IN + h * IWT_W + 2 * lane;
    float2 a  = *(const float2*)(base);
    float2 hh = *(const float2*)(base + PLANE_IN);
    float2 v  = *(const float2*)(base + 2 * PLANE_IN);
    float2 d  = *(const float2*)(base + 3 * PLANE_IN);

    float4 r0, r1;
    {
        float ai = a.x, hi = hh.x, vi = v.x, di = d.x;
        r0.x = (ai + hi + vi + di) * 0.5f;
        r0.y = (ai + hi - vi - di) * 0.5f;
        r1.x = (ai - hi + vi - di) * 0.5f;
        r1.y = (ai - hi - vi + di) * 0.5f;
    }
    {
        float ai = a.y, hi = hh.y, vi = v.y, di = d.y;
        r0.z = (ai + hi + vi + di) * 0.5f;
        r0.w = (ai + hi - vi - di) * 0.5f;
        r1.z = (ai - hi + vi - di) * 0.5f;
        r1.w = (ai - hi - vi + di) * 0.5f;
    }

    // Output plane for channel bc: 128 x 128
    float* o = out + (size_t)bc * PLANE_OUT + (2 * h) * (2 * IWT_W) + 4 * lane;
    *(float4*)(o)              = r0;   // row 2h
    *(float4*)(o + 2 * IWT_W)  = r1;   // row 2h+1
}

extern "C" void kernel_launch(void* const* d_in, const int* in_sizes, int n_in,
                              void* d_out, int out_size) {
    const float* x = (const float*)d_in[0];
    float* out = (float*)d_out;

    // total input elems = 33,554,432 ; 8 elems per thread
    int total = in_sizes[0];
    int threads_total = total / 8;

    int threads = 256;
    int blocks = threads_total / threads;   // 16384
    iwt_kernel<<<blocks, threads>>>(x, out);
}